// round 6
// baseline (speedup 1.0000x reference)
#include <cuda_runtime.h>
#include <cuda_fp16.h>
#include <stdint.h>

#define Bb 4
#define Ss 512
#define Mm 128
#define Hh 768
#define VSIZE 10000

#define ATTN_BLOCKS 128                       // B*(S/32)*2
#define CONV_N8     ((VSIZE * Hh) / 8)        // 960000 uint4 slots
#define CONV_BLOCKS ((CONV_N8 + 255) / 256)   // 3750

// scratch: fp16 value table (15 MB) + partial u (2 MB, [2][B][S][M])
__device__ __half g_vt[(long)VSIZE * Hh];
__device__ float  g_part[2 * Bb * Ss * Mm];

// ---------------------------------------------------------------------------
// Fused kernel: blocks [0,128) do the attention partial GEMM (smem/FMA-bound),
// blocks [128, 128+3750) do the fp32->fp16 table convert (DRAM-bound).
// The two populations overlap on the chip; gather depends on both.
// ---------------------------------------------------------------------------
__global__ __launch_bounds__(256) void kvmn_fused_prep(
    const int*   __restrict__ word_seq,   // [B, M]
    const float* __restrict__ hidden,     // [B, S, H]
    const float* __restrict__ key_table,  // [KEY_SIZE, H]
    const float* __restrict__ vt)         // [VALUE_SIZE, H]
{
    const int t = threadIdx.x;

    if (blockIdx.x >= ATTN_BLOCKS) {
        // ---------------- conv path (no smem, no syncs) ----------------
        long i = (long)(blockIdx.x - ATTN_BLOCKS) * 256 + t;   // one uint4 (8 fp16)
        if (i >= (long)CONV_N8) return;
        float4 a = ((const float4*)vt)[2 * i];
        float4 b = ((const float4*)vt)[2 * i + 1];
        __half2 p0 = __floats2half2_rn(a.x, a.y);
        __half2 p1 = __floats2half2_rn(a.z, a.w);
        __half2 p2 = __floats2half2_rn(b.x, b.y);
        __half2 p3 = __floats2half2_rn(b.z, b.w);
        uint4 r;
        r.x = *(uint32_t*)&p0;  r.y = *(uint32_t*)&p1;
        r.z = *(uint32_t*)&p2;  r.w = *(uint32_t*)&p3;
        ((uint4*)g_vt)[i] = r;
        return;
    }

    // ---------------- attn path ----------------
    __shared__ float sh_e[Mm * 33];   // 128 rows x 32 k, pad 33
    __shared__ float sh_h[32 * 33];   // 32 rows x 32 k
    __shared__ int   sh_idx[Mm];

    const int bid    = blockIdx.x;
    const int hsplit = bid & 1;
    const int stile  = (bid >> 1) & 15;
    const int b      = bid >> 5;
    const int s0     = stile * 32;
    const int h_base = hsplit * (Hh / 2);   // 0 or 384

    if (t < Mm) sh_idx[t] = word_seq[b * Mm + t];
    __syncthreads();

    const int ty = t >> 5;    // 0..7
    const int tx = t & 31;    // 0..31

    float acc[4][4];
#pragma unroll
    for (int i = 0; i < 4; i++)
#pragma unroll
        for (int j = 0; j < 4; j++) acc[i][j] = 0.0f;

    for (int c = 0; c < (Hh / 2) / 32; c++) {    // 12 chunks of 32 k
        const int h0 = h_base + c * 32;
        __syncthreads();
        // sh_e: 128 rows x 32 cols = 1024 float4, 4 per thread
#pragma unroll
        for (int i = 0; i < 4; i++) {
            int f   = t + 256 * i;
            int row = f >> 3;
            int c4  = (f & 7) * 4;
            float4 v = *(const float4*)(key_table + (long)sh_idx[row] * Hh + h0 + c4);
            float* dst = &sh_e[row * 33 + c4];
            dst[0] = v.x; dst[1] = v.y; dst[2] = v.z; dst[3] = v.w;
        }
        // sh_h: 32 rows x 32 cols = 256 float4, 1 per thread
        {
            int row = t >> 3;
            int c4  = (t & 7) * 4;
            float4 v = *(const float4*)(hidden + ((long)(b * Ss + s0 + row)) * Hh + h0 + c4);
            float* dst = &sh_h[row * 33 + c4];
            dst[0] = v.x; dst[1] = v.y; dst[2] = v.z; dst[3] = v.w;
        }
        __syncthreads();
#pragma unroll
        for (int k = 0; k < 32; k++) {
            float hv[4], ev[4];
#pragma unroll
            for (int i = 0; i < 4; i++) hv[i] = sh_h[(ty + 8 * i) * 33 + k];
#pragma unroll
            for (int j = 0; j < 4; j++) ev[j] = sh_e[(tx + 32 * j) * 33 + k];
#pragma unroll
            for (int i = 0; i < 4; i++)
#pragma unroll
                for (int j = 0; j < 4; j++) acc[i][j] += hv[i] * ev[j];
        }
    }

    float* dst = g_part + ((long)hsplit * Bb + b) * Ss * Mm;
#pragma unroll
    for (int i = 0; i < 4; i++)
#pragma unroll
        for (int j = 0; j < 4; j++)
            dst[(s0 + ty + 8 * i) * Mm + (tx + 32 * j)] = acc[i][j];
}

// ---------------------------------------------------------------------------
// Kernel B: fused softmax-combine + fp16 gather-accumulate.
// Grid: B*S = 2048 blocks, 192 threads.
// Threads 0..95 handle m=0..63, 96..191 handle m=64..127 (96 lanes x 16B = row).
// ---------------------------------------------------------------------------
__global__ __launch_bounds__(192) void kvmn_gather_kernel(
    const int*   __restrict__ labels,  // [B, S, M]
    const float* __restrict__ mask,    // [B, S, M]
    float*       __restrict__ out)     // [B, S, H]
{
    __shared__ float sp[Mm];
    __shared__ int   si[Mm];
    __shared__ float osh[Hh];
    __shared__ float wsum[4];

    const int bs = blockIdx.x;
    const int t  = threadIdx.x;
    const float inv_temper = 1.0f / 27.712812921102035f;   // 1/sqrt(768)

    float ev = 0.0f;
    if (t < Mm) {
        long idx = (long)bs * Mm + t;
        float u  = (g_part[idx] + g_part[(long)Bb * Ss * Mm + idx]) * inv_temper;
        float mm = fminf(fmaxf(mask[idx], 0.0f), 1.0f);
        ev = expf(u) * mm;
        si[t] = labels[idx];
    }
    // reduce over the 4 full warps holding t<128
    float v = ev;
    v += __shfl_xor_sync(0xffffffffu, v, 16);
    v += __shfl_xor_sync(0xffffffffu, v, 8);
    v += __shfl_xor_sync(0xffffffffu, v, 4);
    v += __shfl_xor_sync(0xffffffffu, v, 2);
    v += __shfl_xor_sync(0xffffffffu, v, 1);
    if (t < Mm && (t & 31) == 0) wsum[t >> 5] = v;
    __syncthreads();
    float inv = 1.0f / (wsum[0] + wsum[1] + wsum[2] + wsum[3] + 1e-10f);
    if (t < Mm) sp[t] = ev * inv;
    __syncthreads();

    const int half = t / 96;          // 0 or 1
    const int lane = t - half * 96;   // 0..95 -> 16B segment of the fp16 row
    const uint4* V = (const uint4*)g_vt;   // row stride Hh/8 = 96 uint4
    const int m0 = half * 64;

    float a[8];
#pragma unroll
    for (int q = 0; q < 8; q++) a[q] = 0.0f;

#pragma unroll 8
    for (int mi = 0; mi < 64; mi++) {
        const int m = m0 + mi;
        const float w = sp[m];
        uint4 r = V[(long)si[m] * (Hh / 8) + lane];
        // unpack 8 fp16 (exact widening) and fp32-accumulate
        float2 f0 = __half22float2(*(__half2*)&r.x);
        float2 f1 = __half22float2(*(__half2*)&r.y);
        float2 f2 = __half22float2(*(__half2*)&r.z);
        float2 f3 = __half22float2(*(__half2*)&r.w);
        a[0] += w * f0.x;  a[1] += w * f0.y;
        a[2] += w * f1.x;  a[3] += w * f1.y;
        a[4] += w * f2.x;  a[5] += w * f2.y;
        a[6] += w * f3.x;  a[7] += w * f3.y;
    }

    if (half == 0) {
#pragma unroll
        for (int q = 0; q < 8; q++) osh[lane * 8 + q] = a[q];
    }
    __syncthreads();
    if (half == 1) {
        float* op = out + (long)bs * Hh + lane * 8;
#pragma unroll
        for (int q = 0; q < 8; q++) op[q] = a[q] + osh[lane * 8 + q];
    }
}

// ---------------------------------------------------------------------------
extern "C" void kernel_launch(void* const* d_in, const int* in_sizes, int n_in,
                              void* d_out, int out_size)
{
    const int*   word_seq   = (const int*)  d_in[0];  // [B, M]
    const float* hidden     = (const float*)d_in[1];  // [B, S, H]
    const int*   labels     = (const int*)  d_in[2];  // [B, S, M]
    const float* mask       = (const float*)d_in[3];  // [B, S, M]
    const float* key_table  = (const float*)d_in[4];  // [KEY_SIZE, H]
    const float* value_tab  = (const float*)d_in[5];  // [VALUE_SIZE, H]
    float*       out        = (float*)d_out;          // [B, S, H]

    kvmn_fused_prep<<<ATTN_BLOCKS + CONV_BLOCKS, 256>>>(word_seq, hidden,
                                                        key_table, value_tab);
    kvmn_gather_kernel<<<Bb * Ss, 192>>>(labels, mask, out);
}

// round 7
// speedup vs baseline: 1.2667x; 1.2667x over previous
#include <cuda_runtime.h>
#include <cuda_fp16.h>
#include <stdint.h>

#define Bb 4
#define Ss 512
#define Mm 128
#define Hh 768
#define VSIZE 10000
#define NSPLIT 4                 // k-splits of 192
#define PSTRIDE (Bb * Ss * Mm)   // partial-plane stride

// scratch: fp16 value table (15 MB) + partial u (4 MB, [4][B][S][M])
__device__ __half g_vt[(long)VSIZE * Hh];
__device__ float  g_part[NSPLIT * PSTRIDE];

// ---------------------------------------------------------------------------
// Kernel C: convert value_table fp32 -> fp16 (rn). Separate kernel: DO NOT
// co-schedule with the issue-bound attn kernel (R6 regression).
// ---------------------------------------------------------------------------
__global__ __launch_bounds__(256) void kvmn_conv_kernel(const float* __restrict__ vt)
{
    long i = (long)blockIdx.x * 256 + threadIdx.x;          // one uint4 (8 fp16)
    const long n8 = (long)VSIZE * Hh / 8;
    if (i >= n8) return;
    float4 a = ((const float4*)vt)[2 * i];
    float4 b = ((const float4*)vt)[2 * i + 1];
    __half2 p0 = __floats2half2_rn(a.x, a.y);
    __half2 p1 = __floats2half2_rn(a.z, a.w);
    __half2 p2 = __floats2half2_rn(b.x, b.y);
    __half2 p3 = __floats2half2_rn(b.z, b.w);
    uint4 r;
    r.x = *(uint32_t*)&p0;  r.y = *(uint32_t*)&p1;
    r.z = *(uint32_t*)&p2;  r.w = *(uint32_t*)&p3;
    ((uint4*)g_vt)[i] = r;
}

// ---------------------------------------------------------------------------
// Kernel A: partial u. Tile 64s x 128m per block, k-split 4 (192 k each).
// Grid 4b x 8stile x 4split = 128 blocks, 256 threads.
// Thread (ty=t>>5 0..7, tx=t&31): 8s x 4m register tile, s=s0+ty+8i, m=tx+32j.
// k vectorized by 4 via LDS.128 (row stride 36 floats = 144B, 16B-aligned,
// conflict-free: 36 mod 32 = 4 -> lanes spread across all banks).
// ---------------------------------------------------------------------------
#define KP 36   // padded row stride in floats

__global__ __launch_bounds__(256) void kvmn_attn_partial(
    const int*   __restrict__ word_seq,   // [B, M]
    const float* __restrict__ hidden,     // [B, S, H]
    const float* __restrict__ key_table)  // [KEY_SIZE, H]
{
    __shared__ float sh_e[Mm * KP];   // 128 rows x 32 k (pad 36)
    __shared__ float sh_h[64 * KP];   // 64 rows x 32 k
    __shared__ int   sh_idx[Mm];

    const int t      = threadIdx.x;
    const int bid    = blockIdx.x;
    const int hsplit = bid & 3;
    const int stile  = (bid >> 2) & 7;
    const int b      = bid >> 5;
    const int s0     = stile * 64;
    const int h_base = hsplit * (Hh / NSPLIT);   // 0,192,384,576

    if (t < Mm) sh_idx[t] = word_seq[b * Mm + t];
    __syncthreads();

    const int ty = t >> 5;    // 0..7
    const int tx = t & 31;    // 0..31

    float acc[8][4];
#pragma unroll
    for (int i = 0; i < 8; i++)
#pragma unroll
        for (int j = 0; j < 4; j++) acc[i][j] = 0.0f;

    for (int c = 0; c < (Hh / NSPLIT) / 32; c++) {    // 6 chunks of 32 k
        const int h0 = h_base + c * 32;
        __syncthreads();
        // sh_e: 128 rows x 8 float4 = 1024 slots, 4 per thread
#pragma unroll
        for (int i = 0; i < 4; i++) {
            int f   = t + 256 * i;
            int row = f >> 3;
            int c4  = (f & 7) * 4;
            float4 v = *(const float4*)(key_table + (long)sh_idx[row] * Hh + h0 + c4);
            *(float4*)&sh_e[row * KP + c4] = v;
        }
        // sh_h: 64 rows x 8 float4 = 512 slots, 2 per thread
#pragma unroll
        for (int i = 0; i < 2; i++) {
            int f   = t + 256 * i;
            int row = f >> 3;
            int c4  = (f & 7) * 4;
            float4 v = *(const float4*)(hidden + ((long)(b * Ss + s0 + row)) * Hh + h0 + c4);
            *(float4*)&sh_h[row * KP + c4] = v;
        }
        __syncthreads();
#pragma unroll
        for (int k4 = 0; k4 < 8; k4++) {
            float4 ev[4], hv[8];
#pragma unroll
            for (int j = 0; j < 4; j++)
                ev[j] = *(const float4*)&sh_e[(tx + 32 * j) * KP + k4 * 4];
#pragma unroll
            for (int i = 0; i < 8; i++)
                hv[i] = *(const float4*)&sh_h[(ty + 8 * i) * KP + k4 * 4];
#pragma unroll
            for (int i = 0; i < 8; i++)
#pragma unroll
                for (int j = 0; j < 4; j++) {
                    acc[i][j] += hv[i].x * ev[j].x;
                    acc[i][j] += hv[i].y * ev[j].y;
                    acc[i][j] += hv[i].z * ev[j].z;
                    acc[i][j] += hv[i].w * ev[j].w;
                }
        }
    }

    float* dst = g_part + (long)hsplit * PSTRIDE + (long)b * Ss * Mm;
#pragma unroll
    for (int i = 0; i < 8; i++)
#pragma unroll
        for (int j = 0; j < 4; j++)
            dst[(s0 + ty + 8 * i) * Mm + (tx + 32 * j)] = acc[i][j];
}

// ---------------------------------------------------------------------------
// Kernel B: fused softmax-combine + fp16 gather-accumulate.
// Grid: B*S = 2048 blocks, 192 threads.
// Threads 0..95 handle m=0..63, 96..191 handle m=64..127 (96 lanes x 16B/row).
// ---------------------------------------------------------------------------
__global__ __launch_bounds__(192) void kvmn_gather_kernel(
    const int*   __restrict__ labels,  // [B, S, M]
    const float* __restrict__ mask,    // [B, S, M]
    float*       __restrict__ out)     // [B, S, H]
{
    __shared__ float sp[Mm];
    __shared__ int   si[Mm];
    __shared__ float osh[Hh];
    __shared__ float wsum[4];

    const int bs = blockIdx.x;
    const int t  = threadIdx.x;
    const float inv_temper = 1.0f / 27.712812921102035f;   // 1/sqrt(768)

    float ev = 0.0f;
    if (t < Mm) {
        long idx = (long)bs * Mm + t;
        float u = g_part[idx] + g_part[PSTRIDE + idx]
                + g_part[2L * PSTRIDE + idx] + g_part[3L * PSTRIDE + idx];
        u *= inv_temper;
        float mm = fminf(fmaxf(mask[idx], 0.0f), 1.0f);
        ev = expf(u) * mm;
        si[t] = labels[idx];
    }
    // reduce over the 4 full warps holding t<128
    float v = ev;
    v += __shfl_xor_sync(0xffffffffu, v, 16);
    v += __shfl_xor_sync(0xffffffffu, v, 8);
    v += __shfl_xor_sync(0xffffffffu, v, 4);
    v += __shfl_xor_sync(0xffffffffu, v, 2);
    v += __shfl_xor_sync(0xffffffffu, v, 1);
    if (t < Mm && (t & 31) == 0) wsum[t >> 5] = v;
    __syncthreads();
    float inv = 1.0f / (wsum[0] + wsum[1] + wsum[2] + wsum[3] + 1e-10f);
    if (t < Mm) sp[t] = ev * inv;
    __syncthreads();

    const int half = t / 96;          // 0 or 1
    const int lane = t - half * 96;   // 0..95 -> 16B segment of the fp16 row
    const uint4* V = (const uint4*)g_vt;   // row stride Hh/8 = 96 uint4
    const int m0 = half * 64;

    float a[8];
#pragma unroll
    for (int q = 0; q < 8; q++) a[q] = 0.0f;

#pragma unroll 8
    for (int mi = 0; mi < 64; mi++) {
        const int m = m0 + mi;
        const float w = sp[m];
        uint4 r = V[(long)si[m] * (Hh / 8) + lane];
        float2 f0 = __half22float2(*(__half2*)&r.x);
        float2 f1 = __half22float2(*(__half2*)&r.y);
        float2 f2 = __half22float2(*(__half2*)&r.z);
        float2 f3 = __half22float2(*(__half2*)&r.w);
        a[0] += w * f0.x;  a[1] += w * f0.y;
        a[2] += w * f1.x;  a[3] += w * f1.y;
        a[4] += w * f2.x;  a[5] += w * f2.y;
        a[6] += w * f3.x;  a[7] += w * f3.y;
    }

    if (half == 0) {
#pragma unroll
        for (int q = 0; q < 8; q++) osh[lane * 8 + q] = a[q];
    }
    __syncthreads();
    if (half == 1) {
        float* op = out + (long)bs * Hh + lane * 8;
#pragma unroll
        for (int q = 0; q < 8; q++) op[q] = a[q] + osh[lane * 8 + q];
    }
}

// ---------------------------------------------------------------------------
extern "C" void kernel_launch(void* const* d_in, const int* in_sizes, int n_in,
                              void* d_out, int out_size)
{
    const int*   word_seq   = (const int*)  d_in[0];  // [B, M]
    const float* hidden     = (const float*)d_in[1];  // [B, S, H]
    const int*   labels     = (const int*)  d_in[2];  // [B, S, M]
    const float* mask       = (const float*)d_in[3];  // [B, S, M]
    const float* key_table  = (const float*)d_in[4];  // [KEY_SIZE, H]
    const float* value_tab  = (const float*)d_in[5];  // [VALUE_SIZE, H]
    float*       out        = (float*)d_out;          // [B, S, H]

    const int n8 = (VSIZE * Hh) / 8;                  // 960000
    kvmn_conv_kernel<<<(n8 + 255) / 256, 256>>>(value_tab);
    kvmn_attn_partial<<<Bb * 8 * NSPLIT, 256>>>(word_seq, hidden, key_table);
    kvmn_gather_kernel<<<Bb * Ss, 192>>>(labels, mask, out);
}